// round 14
// baseline (speedup 1.0000x reference)
#include <cuda_runtime.h>
#include <cstdint>

// Embedder, single fused kernel. out(x) = w2@relu(w1*x+b1)+b2 is piecewise
// linear in x (<=16 kinks): out[d](x) = A[seg][d]*x + B[seg][d], 17 segs.
// Round-8 gather shape (ONE 32-position chunk per warp, 8-deep gather
// pipeline, 2048 blocks) + cheap staged per-block A/B table build in shared.
// Static one-shot assignment: no persistent loop, no atomics.

#define EMBED_DIM 64
#define NSEG 17

__global__ __launch_bounds__(256, 4) void embedder_fused_kernel(
    const float* __restrict__ input_ids,
    const int*   __restrict__ type_mask,
    const float* __restrict__ emb_table,
    const float* __restrict__ w1,
    const float* __restrict__ b1,
    const float* __restrict__ w2,
    const float* __restrict__ b2,
    float*       __restrict__ out,
    int n_pos)
{
    __shared__ float s_A[NSEG][EMBED_DIM];
    __shared__ float s_B[NSEG][EMBED_DIM];
    __shared__ float s_w2t[16][EMBED_DIM + 1];
    __shared__ float s_w1[16], s_b1[16], s_b2[EMBED_DIM];
    __shared__ float s_t[16];
    __shared__ int   s_rank[16];

    // ---- stage weights coalesced ----
    for (int idx = threadIdx.x; idx < 1024; idx += blockDim.x)
        s_w2t[idx & 15][idx >> 4] = w2[idx];
    if (threadIdx.x < 16) {
        s_w1[threadIdx.x] = w1[threadIdx.x];
        s_b1[threadIdx.x] = b1[threadIdx.x];
    }
    if (threadIdx.x < EMBED_DIM) s_b2[threadIdx.x] = b2[threadIdx.x];
    __syncthreads();

    // ---- thresholds + ranks: 16 threads, once ----
    if (threadIdx.x < 16) {
        const int j = threadIdx.x;
        const float w = s_w1[j], b = s_b1[j];
        s_t[j] = (w != 0.0f) ? (-b / w) : ((b > 0.0f) ? -1e30f : 1e30f);
    }
    __syncthreads();
    if (threadIdx.x < 16) {
        const int j = threadIdx.x;
        const float tj = s_t[j];
        int r = 0;
#pragma unroll
        for (int k = 0; k < 16; ++k)
            r += (s_t[k] < tj) || (s_t[k] == tj && k < j);
        s_rank[j] = r;
    }
    __syncthreads();

    // ---- build A/B: 1088 entries / 256 threads, operands in shared ----
    for (int idx = threadIdx.x; idx < NSEG * EMBED_DIM; idx += blockDim.x) {
        const int seg = idx >> 6;
        const int d   = idx & 63;
        float A = 0.0f, B = s_b2[d];
#pragma unroll
        for (int j = 0; j < 16; ++j) {
            const bool gt = (seg > s_rank[j]);
            const bool active = (s_w1[j] > 0.0f) ? gt
                              : (s_w1[j] < 0.0f) ? !gt
                              : gt;               // w1==0: t=+-1e30 handles it
            if (active) {
                const float w = s_w2t[j][d];
                A = fmaf(w, s_w1[j], A);
                B = fmaf(w, s_b1[j], B);
            }
        }
        s_A[seg][d] = A;
        s_B[seg][d] = B;
    }
    __syncthreads();

    // ---- gather: exactly ONE 32-pos chunk per warp ----
    const int lane = threadIdx.x & 31;
    const int half = lane >> 4;
    const int sub  = lane & 15;
    const int c    = (int)((blockIdx.x * blockDim.x + threadIdx.x) >> 5);
    const int base = c << 5;
    if (base >= n_pos) return;
    const bool full = (base + 32 <= n_pos);
    const int pos_l = base + lane;

    // pk layout: [15:0]=id, [16]=mask, [21:17]=seg
    int pk = 0;
    if (full || pos_l < n_pos) {
        const int id = (int)__ldg(&input_ids[pos_l]);
        const int m  = __ldg(&type_mask[pos_l]);
        const float x = (float)id;
        int seg = 0;
#pragma unroll
        for (int j = 0; j < 16; ++j) seg += (x > s_t[j]);  // broadcast LDS
        pk = id | (m << 16) | (seg << 17);
    }

    const float4* sA4 = reinterpret_cast<const float4*>(&s_A[0][0]);
    const float4* sB4 = reinterpret_cast<const float4*>(&s_B[0][0]);
    float4* out4 = reinterpret_cast<float4*>(out);

#pragma unroll
    for (int p = 0; p < 32; p += 16) {           // 8 pairs per group
        int pks[8]; float4 r[8];
#pragma unroll
        for (int q = 0; q < 8; ++q)
            pks[q] = __shfl_sync(0xffffffffu, pk, p + 2 * q + half);
        // token gathers first: up to 8 independent 256B rows in flight
#pragma unroll
        for (int q = 0; q < 8; ++q) {
            if (pks[q] & 0x10000) {
                const int id = pks[q] & 0xFFFF;
                r[q] = __ldg(reinterpret_cast<const float4*>(
                           emb_table + (size_t)id * 64) + sub);
            }
        }
        // numeric: 2x LDS.128 + fma, overlaps in-flight gathers
#pragma unroll
        for (int q = 0; q < 8; ++q) {
            if (!(pks[q] & 0x10000)) {
                const int sg = pks[q] >> 17;
                const float x = (float)(pks[q] & 0xFFFF);
                const float4 A = sA4[sg * 16 + sub];
                const float4 B = sB4[sg * 16 + sub];
                r[q].x = fmaf(A.x, x, B.x);
                r[q].y = fmaf(A.y, x, B.y);
                r[q].z = fmaf(A.z, x, B.z);
                r[q].w = fmaf(A.w, x, B.w);
            }
        }
        if (full) {
#pragma unroll
            for (int q = 0; q < 8; ++q)
                __stcs(&out4[(size_t)(base + p + 2 * q + half) * 16 + sub], r[q]);
        } else {
#pragma unroll
            for (int q = 0; q < 8; ++q) {
                const int pp = p + 2 * q + half;
                if (base + pp < n_pos)
                    __stcs(&out4[(size_t)(base + pp) * 16 + sub], r[q]);
            }
        }
    }
}

extern "C" void kernel_launch(void* const* d_in, const int* in_sizes, int n_in,
                              void* d_out, int out_size)
{
    const float* input_ids = (const float*)d_in[0];
    const int*   type_mask = (const int*)  d_in[1];
    const float* emb_table = (const float*)d_in[2];
    const float* w1        = (const float*)d_in[3];
    const float* b1        = (const float*)d_in[4];
    const float* w2        = (const float*)d_in[5];
    const float* b2        = (const float*)d_in[6];
    float*       out       = (float*)d_out;

    const int n_pos = in_sizes[0];  // B*S = 524288

    // One 32-position chunk per warp: grid exactly covers nchunk
    const int nchunk = (n_pos + 31) >> 5;
    const int blocks = (nchunk + 7) >> 3;     // 8 warps per block
    embedder_fused_kernel<<<blocks, 256>>>(input_ids, type_mask, emb_table,
                                           w1, b1, w2, b2, out, n_pos);
}

// round 15
// speedup vs baseline: 1.2158x; 1.2158x over previous
#include <cuda_runtime.h>
#include <cstdint>

// Embedder, single fused kernel (round-12 structure + chunk prefetch).
// out(x) = w2@relu(w1*x+b1)+b2 is piecewise linear in x (<=16 kinks):
// out[d](x) = A[seg][d]*x + B[seg][d], 17 segs. Persistent blocks build the
// 8.7KB A/B table in shared, then grid-stride over 32-position chunks.
// The next chunk's id/mask loads are issued while the current chunk is
// processed, hiding the per-chunk L2 latency chain that R12 exposed.

#define EMBED_DIM 64
#define NSEG 17

__global__ __launch_bounds__(256, 4) void embedder_fused_kernel(
    const float* __restrict__ input_ids,
    const int*   __restrict__ type_mask,
    const float* __restrict__ emb_table,
    const float* __restrict__ w1,
    const float* __restrict__ b1,
    const float* __restrict__ w2,
    const float* __restrict__ b2,
    float*       __restrict__ out,
    int n_pos)
{
    __shared__ float s_A[NSEG][EMBED_DIM];
    __shared__ float s_B[NSEG][EMBED_DIM];
    __shared__ float s_w2t[16][EMBED_DIM + 1];
    __shared__ float s_w1[16], s_b1[16], s_b2[EMBED_DIM];
    __shared__ __align__(16) float s_t[16];
    __shared__ int   s_rank[16];

    // ---- stage weights coalesced ----
    for (int idx = threadIdx.x; idx < 1024; idx += blockDim.x)
        s_w2t[idx & 15][idx >> 4] = w2[idx];
    if (threadIdx.x < 16) {
        s_w1[threadIdx.x] = w1[threadIdx.x];
        s_b1[threadIdx.x] = b1[threadIdx.x];
    }
    if (threadIdx.x < EMBED_DIM) s_b2[threadIdx.x] = b2[threadIdx.x];
    __syncthreads();

    // ---- thresholds + ranks: 16 threads, once ----
    if (threadIdx.x < 16) {
        const int j = threadIdx.x;
        const float w = s_w1[j], b = s_b1[j];
        s_t[j] = (w != 0.0f) ? (-b / w) : ((b > 0.0f) ? -1e30f : 1e30f);
    }
    __syncthreads();
    if (threadIdx.x < 16) {
        const int j = threadIdx.x;
        const float tj = s_t[j];
        int r = 0;
#pragma unroll
        for (int k = 0; k < 16; ++k)
            r += (s_t[k] < tj) || (s_t[k] == tj && k < j);
        s_rank[j] = r;
    }
    __syncthreads();

    // ---- build A/B: 1088 entries / 256 threads, operands in shared ----
    for (int idx = threadIdx.x; idx < NSEG * EMBED_DIM; idx += blockDim.x) {
        const int seg = idx >> 6;
        const int d   = idx & 63;
        float A = 0.0f, B = s_b2[d];
#pragma unroll
        for (int j = 0; j < 16; ++j) {
            const bool gt = (seg > s_rank[j]);
            const bool active = (s_w1[j] > 0.0f) ? gt
                              : (s_w1[j] < 0.0f) ? !gt
                              : gt;
            if (active) {
                const float w = s_w2t[j][d];
                A = fmaf(w, s_w1[j], A);
                B = fmaf(w, s_b1[j], B);
            }
        }
        s_A[seg][d] = A;
        s_B[seg][d] = B;
    }
    __syncthreads();

    // ---- persistent gather with chunk prefetch ----
    const int lane  = threadIdx.x & 31;
    const int half  = lane >> 4;
    const int sub   = lane & 15;
    const int warp  = (int)((blockIdx.x * blockDim.x + threadIdx.x) >> 5);
    const int nwarp = (int)((gridDim.x * blockDim.x) >> 5);
    const int nchunk = (n_pos + 31) >> 5;

    const float4* sA4 = reinterpret_cast<const float4*>(&s_A[0][0]);
    const float4* sB4 = reinterpret_cast<const float4*>(&s_B[0][0]);
    const float4* st4 = reinterpret_cast<const float4*>(s_t);
    float4* out4 = reinterpret_cast<float4*>(out);

    // preload first chunk's raw id/mask
    int id_cur = 0, m_cur = 1;
    if (warp < nchunk) {
        const int pos_l = (warp << 5) + lane;
        if (pos_l < n_pos) {
            id_cur = (int)__ldg(&input_ids[pos_l]);
            m_cur  = __ldg(&type_mask[pos_l]);
        }
    }

    for (int c = warp; c < nchunk; c += nwarp) {
        // issue next chunk's loads now; latency hidden under this chunk
        int id_nxt = 0, m_nxt = 1;
        const int cn = c + nwarp;
        if (cn < nchunk) {
            const int pos_n = (cn << 5) + lane;
            if (pos_n < n_pos) {
                id_nxt = (int)__ldg(&input_ids[pos_n]);
                m_nxt  = __ldg(&type_mask[pos_n]);
            }
        }

        // seg from resident registers: 4x LDS.128 + 16 compares
        const float x = (float)id_cur;
        int seg = 0;
#pragma unroll
        for (int g = 0; g < 4; ++g) {
            const float4 t = st4[g];
            seg += (x > t.x) + (x > t.y) + (x > t.z) + (x > t.w);
        }
        const int pk = id_cur | (m_cur << 16) | (seg << 17);

        const int base = c << 5;
        const bool full = (base + 32 <= n_pos);

#pragma unroll
        for (int p = 0; p < 32; p += 8) {            // 4 pairs per group
            int pks[4]; float4 r[4];
#pragma unroll
            for (int q = 0; q < 4; ++q)
                pks[q] = __shfl_sync(0xffffffffu, pk, p + 2 * q + half);
#pragma unroll
            for (int q = 0; q < 4; ++q) {
                if (pks[q] & 0x10000) {
                    const int id = pks[q] & 0xFFFF;
                    r[q] = __ldg(reinterpret_cast<const float4*>(
                               emb_table + (size_t)id * 64) + sub);
                }
            }
#pragma unroll
            for (int q = 0; q < 4; ++q) {
                if (!(pks[q] & 0x10000)) {
                    const int sg = pks[q] >> 17;
                    const float xv = (float)(pks[q] & 0xFFFF);
                    const float4 A = sA4[sg * 16 + sub];
                    const float4 B = sB4[sg * 16 + sub];
                    r[q].x = fmaf(A.x, xv, B.x);
                    r[q].y = fmaf(A.y, xv, B.y);
                    r[q].z = fmaf(A.z, xv, B.z);
                    r[q].w = fmaf(A.w, xv, B.w);
                }
            }
            if (full) {
#pragma unroll
                for (int q = 0; q < 4; ++q)
                    __stcs(&out4[(size_t)(base + p + 2 * q + half) * 16 + sub], r[q]);
            } else {
#pragma unroll
                for (int q = 0; q < 4; ++q) {
                    const int pp = p + 2 * q + half;
                    if (base + pp < n_pos)
                        __stcs(&out4[(size_t)(base + pp) * 16 + sub], r[q]);
                }
            }
        }

        id_cur = id_nxt;
        m_cur  = m_nxt;
    }
}

extern "C" void kernel_launch(void* const* d_in, const int* in_sizes, int n_in,
                              void* d_out, int out_size)
{
    const float* input_ids = (const float*)d_in[0];
    const int*   type_mask = (const int*)  d_in[1];
    const float* emb_table = (const float*)d_in[2];
    const float* w1        = (const float*)d_in[3];
    const float* b1        = (const float*)d_in[4];
    const float* w2        = (const float*)d_in[5];
    const float* b2        = (const float*)d_in[6];
    float*       out       = (float*)d_out;

    const int n_pos = in_sizes[0];  // B*S = 524288

    // Persistent: 148 SMs x 4 resident CTAs
    embedder_fused_kernel<<<592, 256>>>(input_ids, type_mask, emb_table,
                                        w1, b1, w2, b2, out, n_pos);
}